// round 14
// baseline (speedup 1.0000x reference)
#include <cuda_runtime.h>
#include <cuda_fp16.h>
#include <math.h>
#include <stdint.h>

#define BB 2
#define CDIM 128
#define QSPAT 4096   // 16^3
#define NS 512       // 8^3

// ---- scratch (static device globals; no allocation) ----
__device__ __half g_Qh[BB*QSPAT*CDIM];   // [b][pos][c] fp16 (conv + attn A-frags)
__device__ float  g_xs[BB*CDIM*NS];
__device__ __half g_Kh[BB*NS*CDIM];      // [b][key][c] fp16, pre-scaled by 0.25*log2e
__device__ __half g_Vh[BB*CDIM*NS];      // [b][c][key] fp16
__device__ float  g_O [BB*CDIM*QSPAT];

// ---- helpers ----
__device__ __forceinline__ float ex2a(float x) {
    float r; asm("ex2.approx.f32 %0, %1;" : "=f"(r) : "f"(x)); return r;
}
__device__ __forceinline__ uint32_t packh(float lo, float hi) {
    uint32_t r;
    asm("cvt.rn.f16x2.f32 %0, %1, %2;" : "=r"(r) : "f"(hi), "f"(lo));
    return r;
}
__device__ __forceinline__ void mma16(float d[4], const uint32_t a[4],
                                      uint32_t b0, uint32_t b1, const float c[4]) {
    asm("mma.sync.aligned.m16n8k16.row.col.f32.f16.f16.f32 "
        "{%0,%1,%2,%3},{%4,%5,%6,%7},{%8,%9},{%10,%11,%12,%13};"
        : "=f"(d[0]), "=f"(d[1]), "=f"(d[2]), "=f"(d[3])
        : "r"(a[0]), "r"(a[1]), "r"(a[2]), "r"(a[3]),
          "r"(b0), "r"(b1),
          "f"(c[0]), "f"(c[1]), "f"(c[2]), "f"(c[3]));
}

// =====================================================================
// fp16-mma projection GEMM: out[o][p] = bias[o] + sum_c w[o][c]*x[c][p]
// o = c = 128; p-tile 64 per block; 128 threads (4 warps, each 32 o).
// Full K staged once (one sync). Epilogue modes:
//   0: fp32 natural [o][P]         (O projection / final output)
//   1: fp16 natural pairs [o][P]   (V)
//   2: fp16 transposed [p][128c]   (Q, K; scale osc folded in)
// =====================================================================
#define GHS 68            // smem row stride in uint32 words (136 halfs)
#define GH_SMEM ((128 + 64) * GHS * 4)

__global__ __launch_bounds__(128) void gemm_h(
    const float* __restrict__ x, int P,
    const float* __restrict__ w0, const float* __restrict__ b0, void* out0, int mode0, float sc0,
    const float* __restrict__ w1, const float* __restrict__ b1, void* out1, int mode1, float sc1)
{
    const float* w    = blockIdx.z ? w1 : w0;
    const float* bias = blockIdx.z ? b1 : b0;
    void*        outp = blockIdx.z ? out1 : out0;
    const int    mode = blockIdx.z ? mode1 : mode0;
    const float  osc  = blockIdx.z ? sc1 : sc0;

    const int b     = blockIdx.y;
    const int pbase = blockIdx.x * 64;

    extern __shared__ uint32_t smu[];
    uint32_t* whu = smu;               // [128 o][GHS]
    uint32_t* xhu = smu + 128 * GHS;   // [64 p][GHS]

    const int tid  = threadIdx.x;
    const int wi   = tid >> 5;
    const int lane = tid & 31;
    const int r    = lane >> 2;
    const int j    = lane & 3;

    // stage w rows [32wi, 32wi+32) as fp16 pairs
    for (int i = 0; i < 32; i++) {
        int o = wi * 32 + i;
        float2 v0 = *(const float2*)&w[o * 128 + 2 * lane];
        float2 v1 = *(const float2*)&w[o * 128 + 64 + 2 * lane];
        whu[o * GHS + lane]      = packh(v0.x, v0.y);
        whu[o * GHS + 32 + lane] = packh(v1.x, v1.y);
    }
    // stage x transposed [p][c] as fp16 c-pairs
    for (int i = 0; i < 16; i++) {
        int c = 2 * (wi + 4 * i);
        const float* x0 = x + ((size_t)b * 128 + c) * P + pbase;
        const float* x1 = x0 + P;
#pragma unroll
        for (int hf = 0; hf < 2; hf++) {
            int p = hf * 32 + lane;
            xhu[p * GHS + (c >> 1)] = packh(x0[p], x1[p]);
        }
    }
    __syncthreads();

    float acc[2][8][4];
#pragma unroll
    for (int mt = 0; mt < 2; mt++)
#pragma unroll
        for (int nt = 0; nt < 8; nt++)
#pragma unroll
            for (int i = 0; i < 4; i++) acc[mt][nt][i] = 0.f;

    const int ob = wi * 32;
#pragma unroll
    for (int ks = 0; ks < 8; ks++) {
        uint32_t af[2][4];
#pragma unroll
        for (int mt = 0; mt < 2; mt++) {
            int o = ob + mt * 16;
            af[mt][0] = whu[(o + r) * GHS + ks * 8 + j];
            af[mt][1] = whu[(o + r + 8) * GHS + ks * 8 + j];
            af[mt][2] = whu[(o + r) * GHS + ks * 8 + 4 + j];
            af[mt][3] = whu[(o + r + 8) * GHS + ks * 8 + 4 + j];
        }
#pragma unroll
        for (int nt = 0; nt < 8; nt++) {
            uint32_t bf0 = xhu[(nt * 8 + r) * GHS + ks * 8 + j];
            uint32_t bf1 = xhu[(nt * 8 + r) * GHS + ks * 8 + 4 + j];
            mma16(acc[0][nt], af[0], bf0, bf1, acc[0][nt]);
            mma16(acc[1][nt], af[1], bf0, bf1, acc[1][nt]);
        }
    }

    if (mode == 0) {                       // fp32 natural
        float* out = (float*)outp;
#pragma unroll
        for (int mt = 0; mt < 2; mt++) {
            int o0 = ob + mt * 16 + r;
            float bv0 = bias[o0], bv1 = bias[o0 + 8];
#pragma unroll
            for (int nt = 0; nt < 8; nt++) {
                int p = pbase + nt * 8 + 2 * j;
                *(float2*)&out[((size_t)b * 128 + o0) * P + p] =
                    make_float2(acc[mt][nt][0] + bv0, acc[mt][nt][1] + bv0);
                *(float2*)&out[((size_t)b * 128 + o0 + 8) * P + p] =
                    make_float2(acc[mt][nt][2] + bv1, acc[mt][nt][3] + bv1);
            }
        }
    } else if (mode == 1) {                // fp16 natural pairs
        uint32_t* out = (uint32_t*)outp;
        const int Pw = P >> 1;
#pragma unroll
        for (int mt = 0; mt < 2; mt++) {
            int o0 = ob + mt * 16 + r;
            float bv0 = bias[o0], bv1 = bias[o0 + 8];
#pragma unroll
            for (int nt = 0; nt < 8; nt++) {
                int pw = (pbase >> 1) + nt * 4 + j;
                out[((size_t)b * 128 + o0) * Pw + pw] =
                    packh((acc[mt][nt][0] + bv0) * osc, (acc[mt][nt][1] + bv0) * osc);
                out[((size_t)b * 128 + o0 + 8) * Pw + pw] =
                    packh((acc[mt][nt][2] + bv1) * osc, (acc[mt][nt][3] + bv1) * osc);
            }
        }
    } else {                               // fp16 transposed [p][128]
        __syncthreads();
        __half* tr = (__half*)smu;         // [64][136] halfs (272B rows, 16B-aligned)
#pragma unroll
        for (int mt = 0; mt < 2; mt++) {
            int o0 = ob + mt * 16 + r;
            float bv0 = bias[o0], bv1 = bias[o0 + 8];
#pragma unroll
            for (int nt = 0; nt < 8; nt++) {
                int p0 = nt * 8 + 2 * j;
                tr[p0 * 136 + o0]           = __float2half_rn((acc[mt][nt][0] + bv0) * osc);
                tr[(p0 + 1) * 136 + o0]     = __float2half_rn((acc[mt][nt][1] + bv0) * osc);
                tr[p0 * 136 + o0 + 8]       = __float2half_rn((acc[mt][nt][2] + bv1) * osc);
                tr[(p0 + 1) * 136 + o0 + 8] = __float2half_rn((acc[mt][nt][3] + bv1) * osc);
            }
        }
        __syncthreads();
        __half* out = (__half*)outp;
        // 64 rows x 16 uint4 chunks (8 halfs each) = full 128 channels/row
        for (int i = tid; i < 64 * 16; i += 128) {
            int p = i >> 4, seg = i & 15;
            uint4 v = *(const uint4*)&tr[p * 136 + seg * 8];
            *(uint4*)&out[((size_t)b * P + pbase + p) * 128 + seg * 8] = v;
        }
    }
}

// =====================================================================
// Offsets pipeline + trilinear gather (one warp per sample).
// Conv reads g_Qh fp16 [pos][c] -> coalesced 64B per tap.
// =====================================================================
__global__ __launch_bounds__(128) void offset_sample(
    const float* __restrict__ kvf,
    const float* __restrict__ wdw, const float* __restrict__ bdw,
    const float* __restrict__ lnw, const float* __restrict__ lnb,
    const float* __restrict__ wproj)
{
    const int gw   = (blockIdx.x * 128 + threadIdx.x) >> 5;  // 0..4095
    const int lane = threadIdx.x & 31;
    const int bg   = gw >> 9;
    const int samp = gw & 511;
    const int b = bg >> 2, g = bg & 3;
    const int od = samp >> 6, oh = (samp >> 3) & 7, ow = samp & 7;
    const int ch = g * 32 + lane;

    const __half* qt = g_Qh + (size_t)b * QSPAT * 128 + g * 32 + lane;
    const float* wc = wdw + lane * 27;
    float acc = bdw[lane];
    const int z0 = od * 2 - 1, y0 = oh * 2 - 1, x0 = ow * 2 - 1;
#pragma unroll
    for (int kz = 0; kz < 3; kz++) {
        int z = z0 + kz; if ((unsigned)z >= 16u) continue;
#pragma unroll
        for (int ky = 0; ky < 3; ky++) {
            int y = y0 + ky; if ((unsigned)y >= 16u) continue;
#pragma unroll
            for (int kx = 0; kx < 3; kx++) {
                int xq = x0 + kx; if ((unsigned)xq >= 16u) continue;
                acc += wc[kz * 9 + ky * 3 + kx] *
                       __half2float(qt[((z * 16 + y) * 16 + xq) * 128]);
            }
        }
    }

    float s1 = acc, s2 = acc * acc;
#pragma unroll
    for (int o = 16; o; o >>= 1) {
        s1 += __shfl_xor_sync(0xffffffffu, s1, o);
        s2 += __shfl_xor_sync(0xffffffffu, s2, o);
    }
    float mu  = s1 * (1.f / 32.f);
    float var = s2 * (1.f / 32.f) - mu * mu;
    float xn  = (acc - mu) * rsqrtf(var + 1e-5f) * lnw[lane] + lnb[lane];
    float ge = 0.5f * xn * (1.f + erff(xn * 0.70710678118654752440f));

    float pr[3];
#pragma unroll
    for (int i = 0; i < 3; i++) {
        float t = wproj[i * 32 + lane] * ge;
#pragma unroll
        for (int o = 16; o; o >>= 1) t += __shfl_xor_sync(0xffffffffu, t, o);
        pr[i] = t;
    }

    float gz = tanhf(pr[0]) * 0.25f + ((od + 0.5f) * 0.25f - 1.f);
    float gy = tanhf(pr[1]) * 0.25f + ((oh + 0.5f) * 0.25f - 1.f);
    float gx = tanhf(pr[2]) * 0.25f + ((ow + 0.5f) * 0.25f - 1.f);

    float ix = (gx + 1.f) * 0.5f * 15.f;
    float iy = (gy + 1.f) * 0.5f * 15.f;
    float iz = (gz + 1.f) * 0.5f * 15.f;
    float zf = floorf(iz), yf = floorf(iy), xf = floorf(ix);
    float tz = iz - zf, ty = iy - yf, tx = ix - xf;
    int zi = (int)zf, yi = (int)yf, xi = (int)xf;

    const float* kvc = kvf + (b * 128 + ch) * QSPAT;
    float val = 0.f;
#pragma unroll
    for (int dz = 0; dz < 2; dz++) {
        int z = zi + dz; float wz = dz ? tz : 1.f - tz;
        if ((unsigned)z >= 16u) continue;
#pragma unroll
        for (int dy = 0; dy < 2; dy++) {
            int y = yi + dy; float wy = dy ? ty : 1.f - ty;
            if ((unsigned)y >= 16u) continue;
#pragma unroll
            for (int dx = 0; dx < 2; dx++) {
                int xq = xi + dx; float wx = dx ? tx : 1.f - tx;
                if ((unsigned)xq >= 16u) continue;
                val += wz * wy * wx * kvc[(z * 16 + y) * 16 + xq];
            }
        }
    }
    g_xs[(b * 128 + ch) * NS + samp] = val;
}

// =====================================================================
// Attention via fp16 mma m16n8k16 (shuffle-free softmax pipeline).
// Q A-frags loaded straight from g_Qh [pos][c]; K staged by uint4 copy
// from pre-scaled g_Kh [key][c]; V by uint4 row copy from g_Vh [c][key].
// Block 128 thr (4 warps x 32 q), grid (32 qchunks, 16 hb).
// =====================================================================
#define KSTRH 24
#define VSTRH 520
__global__ __launch_bounds__(128) void attn_fp16()
{
    extern __shared__ __half smh[];
    __half* Ks = smh;                  // [512][KSTRH]
    __half* Vs = smh + 512 * KSTRH;    // [16][VSTRH]

    const int hb = blockIdx.y;
    const int b = hb >> 3, h = hb & 7;
    const int tid  = threadIdx.x;
    const int w    = tid >> 5;
    const int lane = tid & 31;

    // stage K (pre-scaled fp16) rows: 32B per key
    const __half* Kb = g_Kh + ((size_t)b * 512) * 128 + h * 16;
    for (int kk = tid; kk < 512; kk += 128) {
        const uint4* s = (const uint4*)(Kb + (size_t)kk * 128);
        uint4 v0 = s[0], v1 = s[1];
        *(uint4*)(Ks + kk * KSTRH) = v0;
        *(uint4*)(Ks + kk * KSTRH + 8) = v1;
    }
    // stage V rows
    const __half* Vb = g_Vh + ((size_t)(b * 128 + h * 16)) * 512;
    for (int i = tid; i < 16 * 64; i += 128) {
        int c = i >> 6, seg = i & 63;
        uint4 v = *(const uint4*)(Vb + (size_t)c * 512 + seg * 8);
        *(uint4*)(Vs + c * VSTRH + seg * 8) = v;
    }
    __syncthreads();

    const int r = lane >> 2;
    const int j = lane & 3;
    const int mq = blockIdx.x * 128 + w * 32;

    // Q A-fragments straight from g_Qh (word index (b*4096+m)*64 + h*8 + j)
    const uint32_t* Qu = (const uint32_t*)g_Qh;
    const size_t qb = ((size_t)b * 4096) * 64 + h * 8 + j;
    uint32_t qa[2][4];
#pragma unroll
    for (int mt = 0; mt < 2; mt++) {
        size_t m = mq + mt * 16;
        qa[mt][0] = Qu[qb + (m + r) * 64];
        qa[mt][1] = Qu[qb + (m + r + 8) * 64];
        qa[mt][2] = Qu[qb + (m + r) * 64 + 4];
        qa[mt][3] = Qu[qb + (m + r + 8) * 64 + 4];
    }

    float o[2][2][4];
    float lsum[2][2];
#pragma unroll
    for (int mt = 0; mt < 2; mt++) {
        lsum[mt][0] = 0.f; lsum[mt][1] = 0.f;
#pragma unroll
        for (int nc = 0; nc < 2; nc++)
#pragma unroll
            for (int i = 0; i < 4; i++) o[mt][nc][i] = 0.f;
    }

    for (int kb = 0; kb < 512; kb += 16) {
        uint32_t kf[2][2];
#pragma unroll
        for (int nt = 0; nt < 2; nt++) {
            const __half* kr = Ks + (kb + 8 * nt + r) * KSTRH;
            kf[nt][0] = *(const uint32_t*)(kr + 2 * j);
            kf[nt][1] = *(const uint32_t*)(kr + 2 * j + 8);
        }
        uint32_t vf[2][2];
#pragma unroll
        for (int nc = 0; nc < 2; nc++) {
            const __half* vr = Vs + (8 * nc + r) * VSTRH + kb;
            vf[nc][0] = *(const uint32_t*)(vr + 2 * j);
            vf[nc][1] = *(const uint32_t*)(vr + 2 * j + 8);
        }
#pragma unroll
        for (int mt = 0; mt < 2; mt++) {
            float s0[4] = {0.f, 0.f, 0.f, 0.f};
            float s1[4] = {0.f, 0.f, 0.f, 0.f};
            mma16(s0, qa[mt], kf[0][0], kf[0][1], s0);
            mma16(s1, qa[mt], kf[1][0], kf[1][1], s1);

            float p00 = ex2a(s0[0]), p01 = ex2a(s0[1]);
            float p02 = ex2a(s0[2]), p03 = ex2a(s0[3]);
            float p10 = ex2a(s1[0]), p11 = ex2a(s1[1]);
            float p12 = ex2a(s1[2]), p13 = ex2a(s1[3]);
            lsum[mt][0] += (p00 + p01) + (p10 + p11);
            lsum[mt][1] += (p02 + p03) + (p12 + p13);

            uint32_t pa[4];
            pa[0] = packh(p00, p01);
            pa[1] = packh(p02, p03);
            pa[2] = packh(p10, p11);
            pa[3] = packh(p12, p13);

            mma16(o[mt][0], pa, vf[0][0], vf[0][1], o[mt][0]);
            mma16(o[mt][1], pa, vf[1][0], vf[1][1], o[mt][1]);
        }
    }

    float* Ob = g_O + (b * 128 + h * 16) * QSPAT;
#pragma unroll
    for (int mt = 0; mt < 2; mt++) {
#pragma unroll
        for (int i = 0; i < 2; i++) {
            lsum[mt][i] += __shfl_xor_sync(0xffffffffu, lsum[mt][i], 1);
            lsum[mt][i] += __shfl_xor_sync(0xffffffffu, lsum[mt][i], 2);
        }
        float i0 = 1.f / lsum[mt][0];
        float i1 = 1.f / lsum[mt][1];
        int m0 = mq + mt * 16 + r;
#pragma unroll
        for (int nc = 0; nc < 2; nc++) {
            int cc = nc * 8 + 2 * j;
            Ob[cc * QSPAT + m0]           = o[mt][nc][0] * i0;
            Ob[(cc + 1) * QSPAT + m0]     = o[mt][nc][1] * i0;
            Ob[cc * QSPAT + m0 + 8]       = o[mt][nc][2] * i1;
            Ob[(cc + 1) * QSPAT + m0 + 8] = o[mt][nc][3] * i1;
        }
    }
}

// =====================================================================
extern "C" void kernel_launch(void* const* d_in, const int* in_sizes, int n_in,
                              void* d_out, int out_size)
{
    (void)in_sizes; (void)n_in; (void)out_size;
    const float* Qf  = (const float*)d_in[0];
    const float* KVf = (const float*)d_in[1];
    const float* wq  = (const float*)d_in[2];
    const float* bq  = (const float*)d_in[3];
    const float* wdw = (const float*)d_in[4];
    const float* bdw = (const float*)d_in[5];
    const float* lnw = (const float*)d_in[6];
    const float* lnb = (const float*)d_in[7];
    const float* wpr = (const float*)d_in[8];
    const float* wk  = (const float*)d_in[9];
    const float* bk  = (const float*)d_in[10];
    const float* wv  = (const float*)d_in[11];
    const float* bv  = (const float*)d_in[12];
    const float* wo  = (const float*)d_in[13];
    const float* bo  = (const float*)d_in[14];
    float* out = (float*)d_out;

    __half *gQh, *gKh, *gVh;
    float *gxs, *gO;
    cudaGetSymbolAddress((void**)&gQh, g_Qh);
    cudaGetSymbolAddress((void**)&gxs, g_xs);
    cudaGetSymbolAddress((void**)&gKh, g_Kh);
    cudaGetSymbolAddress((void**)&gVh, g_Vh);
    cudaGetSymbolAddress((void**)&gO,  g_O);

    const float SC = 0.25f * 1.44269504088896f;   // attn scale * log2(e), folded into K
    const int ATTN_SMEM = (512 * KSTRH + 16 * VSTRH) * 2;   // 41216 B

    cudaFuncSetAttribute(gemm_h,
                         cudaFuncAttributeMaxDynamicSharedMemorySize, GH_SMEM);
    cudaFuncSetAttribute(attn_fp16,
                         cudaFuncAttributeMaxDynamicSharedMemorySize, ATTN_SMEM);

    // 1) Q projection -> fp16 transposed [pos][c]
    gemm_h<<<dim3(QSPAT / 64, BB, 1), 128, GH_SMEM>>>(
        Qf, QSPAT, wq, bq, gQh, 2, 1.0f, wq, bq, gQh, 2, 1.0f);

    // 2) offsets + trilinear gather
    offset_sample<<<1024, 128>>>(KVf, wdw, bdw, lnw, lnb, wpr);

    // 3) K (transposed, pre-scaled) and V (natural) projections
    gemm_h<<<dim3(NS / 64, BB, 2), 128, GH_SMEM>>>(
        gxs, NS, wk, bk, gKh, 2, SC, wv, bv, gVh, 1, 1.0f);

    // 4) attention (fp16 tensor cores)
    attn_fp16<<<dim3(32, 16), 128, ATTN_SMEM>>>();

    // 5) output projection -> fp32 final
    gemm_h<<<dim3(QSPAT / 64, BB, 1), 128, GH_SMEM>>>(
        gO, QSPAT, wo, bo, out, 0, 1.0f, wo, bo, out, 0, 1.0f);
}